// round 1
// baseline (speedup 1.0000x reference)
#include <cuda_runtime.h>
#include <stdint.h>
#include <math.h>

#define FMASK 0xffffffffu

static __device__ __forceinline__ float ex2f(float x){ float y; asm("ex2.approx.f32 %0, %1;" : "=f"(y) : "f"(x)); return y; }
static __device__ __forceinline__ float rcpf(float x){ float y; asm("rcp.approx.f32 %0, %1;" : "=f"(y) : "f"(x)); return y; }
static __device__ __forceinline__ void cp16(uint32_t dst, const void* src){
    asm volatile("cp.async.cg.shared.global [%0], [%1], 16;" :: "r"(dst), "l"(src) : "memory");
}
static __device__ __forceinline__ void cpcommit(){ asm volatile("cp.async.commit_group;" ::: "memory"); }
static __device__ __forceinline__ void cpwait6(){ asm volatile("cp.async.wait_group 6;" ::: "memory"); }
static __device__ __forceinline__ void barsync(int id){ asm volatile("bar.sync %0, 256;" :: "r"(id) : "memory"); }
static __device__ __forceinline__ void bararrive(int id){ asm volatile("bar.arrive %0, 256;" :: "r"(id) : "memory"); }
static __device__ __forceinline__ void membar_cta(){ asm volatile("membar.cta;" ::: "memory"); }

// Named barriers: 1,2 = "chunk full" (ping/pong), 3,4 = "chunk empty" (ping/pong)

__global__ __launch_bounds__(256, 1)
void dynparam_kernel(const float* __restrict__ logits,
                     const float* __restrict__ gum,
                     const float* __restrict__ Amat,
                     const float* __restrict__ Bmat,
                     const float* __restrict__ Cmat,
                     const float* __restrict__ transP,
                     float* __restrict__ out)
{
    constexpr int T = 1024;
    constexpr float SCALE = 2.8853900817779268f;   // (1/tau)*log2(e), tau = 0.5
    constexpr float LOG2E = 1.4426950408889634f;

    __shared__ __align__(16) float ring[8*256];    // logits tile ring (8 steps ahead)
    __shared__ __align__(16) float gring[8*16];    // gumbel ring
    __shared__ __align__(16) float ybuf[2*32*32];  // ping-pong: 32 steps x (16 y | 16 l)

    const int b = blockIdx.x;
    const int tid = threadIdx.x;
    const int w = tid >> 5;
    const int lane = tid & 31;

    float* outA  = out;                 // (B,T,16,16)
    float* outB  = out + 33554432u;     // (B,T,16,8)
    float* outC  = out + 50331648u;     // (B,1,32,16)
    float* outLq = out + 50397184u;     // (B,T)
    float* outLp = out + 50528256u;     // (B,T)

    if (w == 0) {
        // ---------------- scan (producer) warp ----------------
        const int j = lane & 15;                 // lanes 16..31 mirror 0..15 (benign duplicates)
        const float* Lrow = logits + (size_t)b * ((size_t)T * 256);
        const float* grow = gum    + (size_t)b * ((size_t)T * 16);
        uint32_t ring_b  = (uint32_t)__cvta_generic_to_shared(ring);
        uint32_t gring_b = (uint32_t)__cvta_generic_to_shared(gring);

        // prologue: prefetch steps 0..6
        #pragma unroll
        for (int pt = 0; pt < 7; ++pt) {
            uint32_t sb = ring_b + pt*1024 + lane*16;
            const float* gp = Lrow + pt*256 + lane*4;
            cp16(sb, gp);
            cp16(sb + 512, gp + 128);
            if (lane < 4) cp16(gring_b + pt*64 + lane*16, grow + pt*16 + lane*4);
            cpcommit();
        }
        cpwait6();            // slot 0 complete
        __syncwarp();

        float Lc[16], e[16];
        #pragma unroll
        for (int k = 0; k < 16; ++k) { Lc[k] = ring[k*16 + j]; e[k] = 1.0f; }
        float gC = gring[j] * SCALE;
        float rp = 0.0625f;           // 1/S_prev   (y0 uniform => e=1, S=16)
        float rC = rp * SCALE;        // folded coefficient

        for (int t = 0; t < T; ++t) {
            const int p = (t >> 5) & 1;
            if ((t & 31) == 0) barsync(3 + p);   // wait chunk buffer empty

            // prefetch step t+7
            const int ft = t + 7;
            if (ft < T) {
                uint32_t sb = ring_b + (ft & 7)*1024 + lane*16;
                const float* gp = Lrow + (size_t)ft*256 + lane*4;
                cp16(sb, gp);
                cp16(sb + 512, gp + 128);
                if (lane < 4) cp16(gring_b + (ft & 7)*64 + lane*16, grow + ft*16 + lane*4);
            }
            cpcommit();

            // ---- critical chain: u = e . Lcol ; x = u*rC + gC ; en = 2^x ----
            float u0 = e[0]*Lc[0], u1 = e[1]*Lc[1], u2 = e[2]*Lc[2], u3 = e[3]*Lc[3];
            #pragma unroll
            for (int k = 4; k < 16; k += 4) {
                u0 = fmaf(e[k+0], Lc[k+0], u0);
                u1 = fmaf(e[k+1], Lc[k+1], u1);
                u2 = fmaf(e[k+2], Lc[k+2], u2);
                u3 = fmaf(e[k+3], Lc[k+3], u3);
            }
            const float u = (u0+u1)+(u2+u3);
            const float x = fmaf(u, rC, gC);
            const float en = ex2f(x);

            float e2[16];
            #pragma unroll
            for (int k = 0; k < 16; ++k) e2[k] = __shfl_sync(FMASK, en, k);

            // off-chain: store normalized mixed logit l_j = u / S_prev
            float* yb = &ybuf[(p*32 + (t & 31))*32];
            yb[16 + j] = u * rp;

            // off-chain: stage next step's column + gumbel (slot t+1 already landed)
            cpwait6();
            __syncwarp();
            {
                const int s1 = (t + 1) & 7;
                #pragma unroll
                for (int k = 0; k < 16; ++k) Lc[k] = ring[s1*256 + k*16 + j];
                gC = gring[s1*16 + j] * SCALE;
            }

            // in-lane sum tree + rcp (parallel with broadcast consumption)
            const float s0 = (e2[0]+e2[1])+(e2[2]+e2[3]);
            const float s1f = (e2[4]+e2[5])+(e2[6]+e2[7]);
            const float s2 = (e2[8]+e2[9])+(e2[10]+e2[11]);
            const float s3 = (e2[12]+e2[13])+(e2[14]+e2[15]);
            const float S = (s0+s1f)+(s2+s3);
            const float r = rcpf(S);
            rp = r; rC = r * SCALE;
            yb[j] = en * r;                       // normalized y_j for consumers
            #pragma unroll
            for (int k = 0; k < 16; ++k) e[k] = e2[k];

            if ((t & 31) == 31) { membar_cta(); bararrive(1 + p); }  // chunk full
        }
    } else {
        // ---------------- consumer warps ----------------
        bararrive(3); bararrive(4);   // prime both "empty" barriers

        // roles: w in {1,2,3,5} -> A expansion; w in {6,7} -> B expansion; w==4 -> scalars (lq,lp)
        float Ac0[16], Ac1[16], Bc0[16], Bc1[16], logPr[16];
        int eidx = 0;
        const bool isA = (w == 1 || w == 2 || w == 3 || w == 5);
        const bool isB = (w >= 6);
        if (isA) {
            const int aw = (w < 4) ? (w - 1) : 3;
            eidx = (aw*32 + lane)*2;
            #pragma unroll
            for (int k = 0; k < 16; ++k) { Ac0[k] = Amat[k*256 + eidx]; Ac1[k] = Amat[k*256 + eidx + 1]; }
        } else if (isB) {
            const int bw = w - 6;
            eidx = (bw*32 + lane)*2;
            #pragma unroll
            for (int k = 0; k < 16; ++k) { Bc0[k] = Bmat[k*128 + eidx]; Bc1[k] = Bmat[k*128 + eidx + 1]; }
        } else {
            const int i = lane & 15;
            #pragma unroll
            for (int k = 0; k < 16; ++k) logPr[k] = logf(transP[i*16 + k]);
        }

        // C_seq: broadcast Cm[0] (512 floats) into this row's slot
        for (int i = tid - 32; i < 512; i += 224) outC[b*512 + i] = Cmat[i];

        float yp = 0.0625f;  // previous y_i carried by scalar warp
        for (int c = 0; c < 32; ++c) {
            const int p = c & 1;
            barsync(1 + p);   // wait chunk full
            for (int s = 0; s < 32; ++s) {
                const int t = c*32 + s;
                const float* yb = &ybuf[(p*32 + s)*32];
                const float4* yb4 = reinterpret_cast<const float4*>(yb);
                if (isA) {
                    float4 v0 = yb4[0], v1 = yb4[1], v2 = yb4[2], v3 = yb4[3];
                    float ya[16] = {v0.x,v0.y,v0.z,v0.w, v1.x,v1.y,v1.z,v1.w,
                                    v2.x,v2.y,v2.z,v2.w, v3.x,v3.y,v3.z,v3.w};
                    float a0 = ya[0]*Ac0[0], a1 = ya[0]*Ac1[0];
                    #pragma unroll
                    for (int k = 1; k < 16; ++k) { a0 = fmaf(ya[k], Ac0[k], a0); a1 = fmaf(ya[k], Ac1[k], a1); }
                    *reinterpret_cast<float2*>(outA + ((size_t)b*T + t)*256 + eidx) = make_float2(a0, a1);
                } else if (isB) {
                    float4 v0 = yb4[0], v1 = yb4[1], v2 = yb4[2], v3 = yb4[3];
                    float ya[16] = {v0.x,v0.y,v0.z,v0.w, v1.x,v1.y,v1.z,v1.w,
                                    v2.x,v2.y,v2.z,v2.w, v3.x,v3.y,v3.z,v3.w};
                    float a0 = ya[0]*Bc0[0], a1 = ya[0]*Bc1[0];
                    #pragma unroll
                    for (int k = 1; k < 16; ++k) { a0 = fmaf(ya[k], Bc0[k], a0); a1 = fmaf(ya[k], Bc1[k], a1); }
                    *reinterpret_cast<float2*>(outB + ((size_t)b*T + t)*128 + eidx) = make_float2(a0, a1);
                } else {
                    // scalar warp: lq = y.l - lse(l) ; lp = yp^T logP y
                    const int i = lane & 15;
                    const float yj = yb[i], lj = yb[16 + i];
                    float m = lj;
                    #pragma unroll
                    for (int msk = 1; msk < 16; msk <<= 1) m = fmaxf(m, __shfl_xor_sync(FMASK, m, msk));
                    float ee = ex2f((lj - m) * LOG2E);
                    float dd = yj * lj;
                    #pragma unroll
                    for (int msk = 1; msk < 16; msk <<= 1) {
                        ee += __shfl_xor_sync(FMASK, ee, msk);
                        dd += __shfl_xor_sync(FMASK, dd, msk);
                    }
                    const float lq = dd - (m + logf(ee));
                    float4 v0 = yb4[0], v1 = yb4[1], v2 = yb4[2], v3 = yb4[3];
                    float ya[16] = {v0.x,v0.y,v0.z,v0.w, v1.x,v1.y,v1.z,v1.w,
                                    v2.x,v2.y,v2.z,v2.w, v3.x,v3.y,v3.z,v3.w};
                    float a = ya[0]*logPr[0];
                    #pragma unroll
                    for (int k = 1; k < 16; ++k) a = fmaf(ya[k], logPr[k], a);
                    float term = yp * a;
                    #pragma unroll
                    for (int msk = 1; msk < 16; msk <<= 1) term += __shfl_xor_sync(FMASK, term, msk);
                    const float lp = (t == 0) ? -2.7725887222397811f : term;  // -log(16) at t=0
                    if (lane == 0) { outLq[(size_t)b*T + t] = lq; outLp[(size_t)b*T + t] = lp; }
                    yp = yj;
                }
            }
            bararrive(3 + p);   // chunk empty
        }
    }
}

extern "C" void kernel_launch(void* const* d_in, const int* in_sizes, int n_in,
                              void* d_out, int out_size)
{
    const float *logits = nullptr, *gum = nullptr, *A = nullptr, *Bm = nullptr,
                *Cm = nullptr, *tP = nullptr;
    for (int i = 0; i < n_in; ++i) {
        switch (in_sizes[i]) {
            case 33554432: logits = (const float*)d_in[i]; break;  // (128,1024,16,16)
            case 2097152:  gum    = (const float*)d_in[i]; break;  // (128,1024,16)
            case 4096:     A      = (const float*)d_in[i]; break;  // (16,16,16)
            case 2048:     Bm     = (const float*)d_in[i]; break;  // (16,16,8)
            case 8192:     Cm     = (const float*)d_in[i]; break;  // (16,32,16)
            case 256:      tP     = (const float*)d_in[i]; break;  // (16,16)
        }
    }
    (void)out_size;
    dynparam_kernel<<<128, 256>>>(logits, gum, A, Bm, Cm, tP, (float*)d_out);
}

// round 3
// speedup vs baseline: 1.4182x; 1.4182x over previous
#include <cuda_runtime.h>
#include <stdint.h>
#include <math.h>

#define FMASK 0xffffffffu

static __device__ __forceinline__ float ex2f(float x){ float y; asm("ex2.approx.f32 %0, %1;" : "=f"(y) : "f"(x)); return y; }
static __device__ __forceinline__ float lg2f(float x){ float y; asm("lg2.approx.f32 %0, %1;" : "=f"(y) : "f"(x)); return y; }
static __device__ __forceinline__ float rcpf(float x){ float y; asm("rcp.approx.f32 %0, %1;" : "=f"(y) : "f"(x)); return y; }
static __device__ __forceinline__ void cp16(uint32_t dst, const void* src){
    asm volatile("cp.async.cg.shared.global [%0], [%1], 16;" :: "r"(dst), "l"(src) : "memory");
}
static __device__ __forceinline__ void cpcommit(){ asm volatile("cp.async.commit_group;" ::: "memory"); }
static __device__ __forceinline__ void cpwait14(){ asm volatile("cp.async.wait_group 14;" ::: "memory"); }
static __device__ __forceinline__ void barsync(int id){ asm volatile("bar.sync %0, 256;" :: "r"(id) : "memory"); }
static __device__ __forceinline__ void bararrive(int id){ asm volatile("bar.arrive %0, 256;" :: "r"(id) : "memory"); }
static __device__ __forceinline__ void membar_cta(){ asm volatile("membar.cta;" ::: "memory"); }

// Named barriers: 1,2 = "chunk full" (ping/pong), 3,4 = "chunk empty" (ping/pong)

__global__ __launch_bounds__(256, 1)
void dynparam_kernel(const float* __restrict__ logits,
                     const float* __restrict__ gum,
                     const float* __restrict__ Amat,
                     const float* __restrict__ Bmat,
                     const float* __restrict__ Cmat,
                     const float* __restrict__ transP,
                     float* __restrict__ out)
{
    constexpr int T = 1024;
    constexpr float SCALE = 2.8853900817779268f;   // (1/tau)*log2(e), tau = 0.5
    constexpr float LOG2E = 1.4426950408889634f;
    constexpr float LN2   = 0.6931471805599453f;

    __shared__ __align__(16) float ring[16*256];    // logits ring, 16 slots (15 ahead)
    __shared__ __align__(16) float gring[16*16];    // gumbel ring
    __shared__ __align__(16) float ybuf[2*32*16];   // ping-pong rows: y[16] per step (A/B warps)
    __shared__ __align__(16) float ytr[2][16*33];   // transposed y (scalar warp), stride 33
    __shared__ __align__(16) float ltr[2][16*33];   // transposed l (scalar warp)
    __shared__ __align__(16) float4 lgPs4[64];      // log(transP), 16x16 as float4

    const int b = blockIdx.x;
    const int tid = threadIdx.x;
    const int w = tid >> 5;
    const int lane = tid & 31;

    float* outA  = out;                 // (B,T,16,16)
    float* outB  = out + 33554432u;     // (B,T,16,8)
    float* outC  = out + 50331648u;     // (B,1,32,16)
    float* outLq = out + 50397184u;     // (B,T)
    float* outLp = out + 50528256u;     // (B,T)

    if (w == 0) {
        // ---------------- scan (producer) warp, SMSP0 ----------------
        const int j = lane & 15;                 // lanes 16..31 mirror 0..15
        const bool wr = (lane < 16);
        const float* Lrow = logits + (size_t)b * ((size_t)T * 256);
        const float* grow = gum    + (size_t)b * ((size_t)T * 16);
        uint32_t ring_b  = (uint32_t)__cvta_generic_to_shared(ring);
        uint32_t gring_b = (uint32_t)__cvta_generic_to_shared(gring);

        // prologue: prefetch steps 0..14
        #pragma unroll
        for (int pt = 0; pt < 15; ++pt) {
            uint32_t sb = ring_b + pt*1024 + lane*16;
            const float* gp = Lrow + pt*256 + lane*4;
            cp16(sb, gp);
            cp16(sb + 512, gp + 128);
            if (lane < 4) cp16(gring_b + pt*64 + lane*16, grow + pt*16 + lane*4);
            cpcommit();
        }
        cpwait14();            // slot 0 complete
        __syncwarp();

        float Lc[16], ea[16], eb[16];
        #pragma unroll
        for (int k = 0; k < 16; ++k) { Lc[k] = ring[k*16 + j]; ea[k] = 1.0f; }
        float gC = gring[j] * SCALE;
        float rp = 0.0625f;           // 1/S_prev   (y0 uniform)
        float rC = rp * SCALE;        // folded coefficient

#define SCAN_SUBSTEP(EIN, EOUT, TT)                                                      \
        {                                                                                \
            const int p_ = ((TT) >> 5) & 1;                                              \
            const int st = (TT) & 31;                                                    \
            if (st == 0) barsync(3 + p_);                                                \
            {   const int ft = (TT) + 15;                                                \
                if (ft < T) {                                                            \
                    uint32_t sb = ring_b + (ft & 15)*1024 + lane*16;                     \
                    const float* gp = Lrow + (size_t)ft*256 + lane*4;                    \
                    cp16(sb, gp);                                                        \
                    cp16(sb + 512, gp + 128);                                            \
                    if (lane < 4) cp16(gring_b + (ft & 15)*64 + lane*16,                 \
                                       grow + (size_t)ft*16 + lane*4);                   \
                }                                                                        \
                cpcommit();                                                              \
            }                                                                            \
            float u0 = EIN[0]*Lc[0], u1 = EIN[1]*Lc[1], u2 = EIN[2]*Lc[2], u3 = EIN[3]*Lc[3]; \
            _Pragma("unroll")                                                            \
            for (int k = 4; k < 16; k += 4) {                                            \
                u0 = fmaf(EIN[k+0], Lc[k+0], u0);                                        \
                u1 = fmaf(EIN[k+1], Lc[k+1], u1);                                        \
                u2 = fmaf(EIN[k+2], Lc[k+2], u2);                                        \
                u3 = fmaf(EIN[k+3], Lc[k+3], u3);                                        \
            }                                                                            \
            const float u = (u0+u1)+(u2+u3);                                             \
            const float x = fmaf(u, rC, gC);                                             \
            const float en = ex2f(x);                                                    \
            _Pragma("unroll")                                                            \
            for (int k = 0; k < 16; ++k) EOUT[k] = __shfl_sync(FMASK, en, k);            \
            if (wr) ltr[p_][j*33 + st] = u * rp;                                         \
            cpwait14();                                                                  \
            __syncwarp();                                                                \
            {   const int s1 = ((TT) + 1) & 15;                                          \
                _Pragma("unroll")                                                        \
                for (int k = 0; k < 16; ++k) Lc[k] = ring[s1*256 + k*16 + j];            \
                gC = gring[s1*16 + j] * SCALE;                                           \
            }                                                                            \
            const float sA = (EOUT[0]+EOUT[1])+(EOUT[2]+EOUT[3]);                        \
            const float sB = (EOUT[4]+EOUT[5])+(EOUT[6]+EOUT[7]);                        \
            const float sC = (EOUT[8]+EOUT[9])+(EOUT[10]+EOUT[11]);                      \
            const float sD = (EOUT[12]+EOUT[13])+(EOUT[14]+EOUT[15]);                    \
            const float S = (sA+sB)+(sC+sD);                                             \
            const float r = rcpf(S);                                                     \
            const float yn = en * r;                                                     \
            rp = r; rC = r * SCALE;                                                      \
            if (wr) { ybuf[(p_*32 + st)*16 + j] = yn; ytr[p_][j*33 + st] = yn; }         \
            if (st == 31) { membar_cta(); bararrive(1 + p_); }                           \
        }

        for (int t = 0; t < T; t += 2) {
            SCAN_SUBSTEP(ea, eb, t)
            SCAN_SUBSTEP(eb, ea, t + 1)
        }
#undef SCAN_SUBSTEP
    } else if (w == 4) {
        // ---------------- scalar warp (lq, lp), SMSP0, lane-per-timestep ----------------
        bararrive(3); bararrive(4);   // prime empty barriers

        // log(transP) into shared (this warp is its only reader)
        float* lgP = (float*)lgPs4;
        for (int i = lane; i < 256; i += 32) lgP[i] = logf(transP[i]);
        __syncwarp();

        // C_seq contribution (shared with other consumers' pattern)
        for (int i = tid - 32; i < 512; i += 224) outC[b*512 + i] = Cmat[i];

        const int s = lane;
        const int sm = (s == 0) ? 0 : (s - 1);
        float yp0[16];
        #pragma unroll
        for (int k = 0; k < 16; ++k) yp0[k] = 0.0625f;

        for (int c = 0; c < 32; ++c) {
            const int p = c & 1;
            barsync(1 + p);   // wait chunk full
            const int t = c*32 + s;

            float yj[16], lj[16], ypj[16];
            #pragma unroll
            for (int k = 0; k < 16; ++k) {
                yj[k] = ytr[p][k*33 + s];
                lj[k] = ltr[p][k*33 + s];
                const float yv = ytr[p][k*33 + sm];
                ypj[k] = (s == 0) ? yp0[k] : yv;
            }

            // lq = dot(y,l) - lse(l)   (l bounded ~±6, shift-free is safe)
            float dd = 0.0f, ee = 0.0f;
            #pragma unroll
            for (int k = 0; k < 16; ++k) {
                dd = fmaf(yj[k], lj[k], dd);
                ee += ex2f(lj[k] * LOG2E);
            }
            const float lq = dd - lg2f(ee) * LN2;

            // lp = yprev^T logP y
            float acc = 0.0f;
            #pragma unroll
            for (int i = 0; i < 16; ++i) {
                const float4 r0 = lgPs4[i*4+0], r1 = lgPs4[i*4+1];
                const float4 r2 = lgPs4[i*4+2], r3 = lgPs4[i*4+3];
                float wv =        yj[0]*r0.x;
                wv = fmaf(yj[1],  r0.y, wv); wv = fmaf(yj[2],  r0.z, wv); wv = fmaf(yj[3],  r0.w, wv);
                wv = fmaf(yj[4],  r1.x, wv); wv = fmaf(yj[5],  r1.y, wv); wv = fmaf(yj[6],  r1.z, wv);
                wv = fmaf(yj[7],  r1.w, wv); wv = fmaf(yj[8],  r2.x, wv); wv = fmaf(yj[9],  r2.y, wv);
                wv = fmaf(yj[10], r2.z, wv); wv = fmaf(yj[11], r2.w, wv); wv = fmaf(yj[12], r3.x, wv);
                wv = fmaf(yj[13], r3.y, wv); wv = fmaf(yj[14], r3.z, wv); wv = fmaf(yj[15], r3.w, wv);
                acc = fmaf(ypj[i], wv, acc);
            }
            const float lp = (t == 0) ? -2.7725887222397811f : acc;  // -log(16) at t=0

            outLq[(size_t)b*T + t] = lq;
            outLp[(size_t)b*T + t] = lp;

            // carry last y of this chunk to lane 0 for next chunk
            #pragma unroll
            for (int k = 0; k < 16; ++k) yp0[k] = __shfl_sync(FMASK, yj[k], 31);

            bararrive(3 + p);   // chunk empty
        }
    } else {
        // ---------------- A/B expansion warps ----------------
        bararrive(3); bararrive(4);   // prime empty barriers

        // SMSP plan: A on w1,w5 (SMSP1) and w2,w6 (SMSP2); B on w3,w7 (SMSP3)
        const bool isA = (w == 1 || w == 2 || w == 5 || w == 6);
        float Mc0[16], Mc1[16];
        int eidx;
        float* outM;
        int stride;
        if (isA) {
            const int aw = (w < 4) ? (w - 1) : (w - 3);   // w1->0, w2->1, w5->2, w6->3
            eidx = (aw*32 + lane)*2;
            #pragma unroll
            for (int k = 0; k < 16; ++k) { Mc0[k] = Amat[k*256 + eidx]; Mc1[k] = Amat[k*256 + eidx + 1]; }
            outM = outA; stride = 256;
        } else {
            const int bw = (w == 3) ? 0 : 1;
            eidx = (bw*32 + lane)*2;
            #pragma unroll
            for (int k = 0; k < 16; ++k) { Mc0[k] = Bmat[k*128 + eidx]; Mc1[k] = Bmat[k*128 + eidx + 1]; }
            outM = outB; stride = 128;
        }

        // C_seq: broadcast Cm[0]
        for (int i = tid - 32; i < 512; i += 224) outC[b*512 + i] = Cmat[i];

        for (int c = 0; c < 32; ++c) {
            const int p = c & 1;
            barsync(1 + p);   // wait chunk full
            #pragma unroll 4
            for (int s = 0; s < 32; ++s) {
                const int t = c*32 + s;
                const float4* yb4 = reinterpret_cast<const float4*>(&ybuf[(p*32 + s)*16]);
                const float4 v0 = yb4[0], v1 = yb4[1], v2 = yb4[2], v3 = yb4[3];
                const float ya[16] = {v0.x,v0.y,v0.z,v0.w, v1.x,v1.y,v1.z,v1.w,
                                      v2.x,v2.y,v2.z,v2.w, v3.x,v3.y,v3.z,v3.w};
                float a0 = ya[0]*Mc0[0], a1 = ya[0]*Mc1[0];
                #pragma unroll
                for (int k = 1; k < 16; ++k) { a0 = fmaf(ya[k], Mc0[k], a0); a1 = fmaf(ya[k], Mc1[k], a1); }
                *reinterpret_cast<float2*>(outM + ((size_t)b*T + t)*stride + eidx) = make_float2(a0, a1);
            }
            bararrive(3 + p);   // chunk empty
        }
    }
}

extern "C" void kernel_launch(void* const* d_in, const int* in_sizes, int n_in,
                              void* d_out, int out_size)
{
    const float *logits = nullptr, *gum = nullptr, *A = nullptr, *Bm = nullptr,
                *Cm = nullptr, *tP = nullptr;
    for (int i = 0; i < n_in; ++i) {
        switch (in_sizes[i]) {
            case 33554432: logits = (const float*)d_in[i]; break;  // (128,1024,16,16)
            case 2097152:  gum    = (const float*)d_in[i]; break;  // (128,1024,16)
            case 4096:     A      = (const float*)d_in[i]; break;  // (16,16,16)
            case 2048:     Bm     = (const float*)d_in[i]; break;  // (16,16,8)
            case 8192:     Cm     = (const float*)d_in[i]; break;  // (16,32,16)
            case 256:      tP     = (const float*)d_in[i]; break;  // (16,16)
        }
    }
    (void)out_size;
    dynparam_kernel<<<128, 256>>>(logits, gum, A, Bm, Cm, tP, (float*)d_out);
}